// round 2
// baseline (speedup 1.0000x reference)
#include <cuda_runtime.h>
#include <math.h>

// ---------------------------------------------------------------------------
// TransactionGNN: 2-layer GAT (H=4, C=64) + MLP head. Output depends only on
// node N-1 (ctx = x[-1]) -> compute only its 2-hop in-cone.
// ---------------------------------------------------------------------------

#define HEADS 4
#define HC    256           // HEADS*OUT
#define DIN   64

#define NMAX  262144        // max nodes (N = 50000 in practice)
#define MAX2  2048          // cap: edges with dst == N-1
#define MAXS1 2049          // cap: |S1|
#define MAXE1 65536         // cap: edges with dst in S1 (+ self loops)
#define MAXN0 8192          // cap: |S0|
#define MAXDEG 1024         // cap: in-degree per S1 node

// ------------------------- device scratch (static) -------------------------
__device__ int   g_cnt2, g_cntS1, g_cntE1, g_cnt0;
__device__ int   g_L2src[MAX2];
__device__ int   g_S1[MAXS1];
__device__ int   g_E1src[MAXE1], g_E1dst[MAXE1];
__device__ int   g_idx1[NMAX];            // node -> S1 index (or -1)
__device__ int   g_idx0[NMAX];            // node -> S0 index (or -1/-2)
__device__ int   g_S0[MAXN0];
__device__ float g_h0[MAXN0 * HC];
__device__ float g_als0[MAXN0 * HEADS], g_ald0[MAXN0 * HEADS];
__device__ float g_x1[MAXS1 * HC];
__device__ float g_h1[MAXS1 * HC];
__device__ float g_als1[MAXS1 * HEADS], g_ald1[MAXS1 * HEADS];
__device__ float g_ctx[HC];
__device__ float g_hmid[DIN];

// ------------------------------- kernels -----------------------------------

__global__ void k_init(int N) {
    int i = blockIdx.x * blockDim.x + threadIdx.x;
    if (i < N) { g_idx1[i] = -1; g_idx0[i] = -1; }
    if (i == 0) { g_cnt2 = 0; g_cntS1 = 0; g_cntE1 = 0; g_cnt0 = 0; }
}

// collect srcs of edges whose dst is the context node
__global__ void k_scan2(const int* __restrict__ src, const int* __restrict__ dst,
                        int E, int nTarget) {
    int i = blockIdx.x * blockDim.x + threadIdx.x;
    if (i < E && __ldg(dst + i) == nTarget) {
        int p = atomicAdd(&g_cnt2, 1);
        if (p < MAX2) g_L2src[p] = src[i];
    }
}

// dedup -> S1 (context node gets index 0); also:
//   - append one self-loop edge per S1 node into E1 (add_self_loops=True)
//   - register S1 nodes in S0 (indices 0..|S1|-1)
__global__ void k_buildS1(int nTarget) {
    __shared__ int ssrc[MAX2];
    __shared__ int slist[MAXS1];
    __shared__ int scount;
    int n2 = min(g_cnt2, MAX2);
    for (int i = threadIdx.x; i < n2; i += blockDim.x) ssrc[i] = g_L2src[i];
    __syncthreads();
    if (threadIdx.x == 0) {
        int c = 0;
        slist[c++] = nTarget;
        for (int e = 0; e < n2; e++) {
            int s = ssrc[e];
            bool dup = false;
            for (int k = 0; k < c; k++) if (slist[k] == s) { dup = true; break; }
            if (!dup) slist[c++] = s;
        }
        scount = c; g_cntS1 = c; g_cnt2 = n2;
        g_cntE1 = c;            // first c slots of E1 = self loops
        g_cnt0  = c;            // first c slots of S0 = S1 nodes
    }
    __syncthreads();
    for (int i = threadIdx.x; i < scount; i += blockDim.x) {
        int u = slist[i];
        g_S1[i] = u;
        g_idx1[u] = i;
        g_E1src[i] = u; g_E1dst[i] = u;   // self loop
        g_S0[i] = u;  g_idx0[u] = i;      // S0 registration
    }
}

// collect every non-self-loop edge whose dst is in S1; register new srcs in S0
__global__ void k_scanE1(const int* __restrict__ src, const int* __restrict__ dst, int E) {
    int i = blockIdx.x * blockDim.x + threadIdx.x;
    if (i < E) {
        int d = __ldg(dst + i);
        if (g_idx1[d] >= 0) {
            int s = src[i];
            int p = atomicAdd(&g_cntE1, 1);
            if (p < MAXE1) { g_E1src[p] = s; g_E1dst[p] = d; }
            int old = atomicCAS(&g_idx0[s], -1, -2);
            if (old == -1) {
                int q = atomicAdd(&g_cnt0, 1);
                if (q < MAXN0) { g_S0[q] = s; g_idx0[s] = q; }
                else g_idx0[s] = 0;   // overflow guard (never in practice)
            }
        }
    }
}

// h0 = emb[y[n]] @ W0   (per S0 node), plus attention logits al_s0 / al_d0
__global__ void k_h0(const int* __restrict__ y, const float* __restrict__ emb,
                     const float* __restrict__ W0,
                     const float* __restrict__ as0, const float* __restrict__ ad0) {
    __shared__ float xin[DIN];
    __shared__ float red[HC];
    int j = threadIdx.x, h = j >> 6;
    int n0 = min(g_cnt0, MAXN0);
    for (int b = blockIdx.x; b < n0; b += gridDim.x) {
        int node = g_S0[b];
        if (j < DIN) xin[j] = emb[(long long)y[node] * DIN + j];
        __syncthreads();
        float acc = 0.f;
        #pragma unroll
        for (int d = 0; d < DIN; d++) acc += xin[d] * W0[d * HC + j];
        g_h0[b * HC + j] = acc;
        // al_src: per-head (64-wide segments)
        red[j] = acc * as0[j];
        __syncthreads();
        for (int s = 32; s >= 1; s >>= 1) {
            if ((j & 63) < s) red[j] += red[j + s];
            __syncthreads();
        }
        if ((j & 63) == 0) g_als0[b * HEADS + h] = red[j];
        __syncthreads();
        // al_dst
        red[j] = acc * ad0[j];
        __syncthreads();
        for (int s = 32; s >= 1; s >>= 1) {
            if ((j & 63) < s) red[j] += red[j + s];
            __syncthreads();
        }
        if ((j & 63) == 0) g_ald0[b * HEADS + h] = red[j];
        __syncthreads();
    }
}

// layer-1 GAT for each S1 node: softmax over incoming edges, aggregate,
// + b0, ELU, L2 normalize -> g_x1
__global__ void k_layer1(const float* __restrict__ b0) {
    __shared__ int   medge[MAXDEG];
    __shared__ int   s_mc;
    __shared__ float m4[HEADS], den4[HEADS];
    __shared__ float red[HC];
    int j = threadIdx.x, h = j >> 6;
    int nS1 = g_cntS1;
    int nE  = min(g_cntE1, MAXE1);
    for (int b = blockIdx.x; b < nS1; b += gridDim.x) {
        int dstNode = g_S1[b];
        if (j == 0) s_mc = 0;
        __syncthreads();
        for (int e = j; e < nE; e += blockDim.x)
            if (g_E1dst[e] == dstNode) {
                int p = atomicAdd(&s_mc, 1);
                if (p < MAXDEG) medge[p] = e;
            }
        __syncthreads();
        int mc = min(s_mc, MAXDEG);
        int id_d = g_idx0[dstNode];
        float ald = g_ald0[id_d * HEADS + h];
        // max
        float lmax = -INFINITY;
        for (int k = (j & 63); k < mc; k += 64) {
            int i0 = g_idx0[g_E1src[medge[k]]];
            float ev = g_als0[i0 * HEADS + h] + ald;
            ev = ev >= 0.f ? ev : 0.2f * ev;
            lmax = fmaxf(lmax, ev);
        }
        red[j] = lmax; __syncthreads();
        for (int s = 32; s >= 1; s >>= 1) {
            if ((j & 63) < s) red[j] = fmaxf(red[j], red[j + s]);
            __syncthreads();
        }
        if ((j & 63) == 0) m4[h] = red[j];
        __syncthreads();
        // sum exp
        float lsum = 0.f;
        for (int k = (j & 63); k < mc; k += 64) {
            int i0 = g_idx0[g_E1src[medge[k]]];
            float ev = g_als0[i0 * HEADS + h] + ald;
            ev = ev >= 0.f ? ev : 0.2f * ev;
            lsum += expf(ev - m4[h]);
        }
        red[j] = lsum; __syncthreads();
        for (int s = 32; s >= 1; s >>= 1) {
            if ((j & 63) < s) red[j] += red[j + s];
            __syncthreads();
        }
        if ((j & 63) == 0) den4[h] = red[j];
        __syncthreads();
        // aggregate channel j
        float invden = 1.f / (den4[h] + 1e-16f);
        float mm = m4[h];
        float outv = 0.f;
        for (int k = 0; k < mc; k++) {
            int i0 = g_idx0[g_E1src[medge[k]]];
            float ev = g_als0[i0 * HEADS + h] + ald;
            ev = ev >= 0.f ? ev : 0.2f * ev;
            outv += expf(ev - mm) * invden * g_h0[i0 * HC + j];
        }
        outv += b0[j];
        outv = outv > 0.f ? outv : (expf(outv) - 1.f);       // ELU
        // L2 normalize over 256 channels
        red[j] = outv * outv;
        for (int s = 128; s >= 1; s >>= 1) {
            __syncthreads();
            if (j < s) red[j] += red[j + s];
        }
        __syncthreads();
        float nv = fmaxf(sqrtf(red[0]), 1e-12f);
        g_x1[b * HC + j] = outv / nv;
        __syncthreads();
    }
}

// h1 = x1 @ W1 for each S1 node, plus attention logits
__global__ void k_h1(const float* __restrict__ W1,
                     const float* __restrict__ as1, const float* __restrict__ ad1) {
    __shared__ float xin[HC];
    __shared__ float red[HC];
    int j = threadIdx.x, h = j >> 6;
    int nS1 = g_cntS1;
    for (int b = blockIdx.x; b < nS1; b += gridDim.x) {
        xin[j] = g_x1[b * HC + j];
        __syncthreads();
        float acc = 0.f;
        #pragma unroll 8
        for (int k = 0; k < HC; k++) acc += xin[k] * W1[k * HC + j];
        g_h1[b * HC + j] = acc;
        red[j] = acc * as1[j];
        __syncthreads();
        for (int s = 32; s >= 1; s >>= 1) {
            if ((j & 63) < s) red[j] += red[j + s];
            __syncthreads();
        }
        if ((j & 63) == 0) g_als1[b * HEADS + h] = red[j];
        __syncthreads();
        red[j] = acc * ad1[j];
        __syncthreads();
        for (int s = 32; s >= 1; s >>= 1) {
            if ((j & 63) < s) red[j] += red[j + s];
            __syncthreads();
        }
        if ((j & 63) == 0) g_ald1[b * HEADS + h] = red[j];
        __syncthreads();
    }
}

// layer-2 GAT only at the context node (S1 index 0) -> g_ctx
__global__ void k_layer2(const float* __restrict__ b1) {
    __shared__ float m4[HEADS], den4[HEADS];
    __shared__ float red[HC];
    int j = threadIdx.x, h = j >> 6;
    int n2 = g_cnt2;
    int nEdges = n2 + 1;               // + self loop (src = context, i1 = 0)
    float ald = g_ald1[h];             // dst index in S1 is 0
    float lmax = -INFINITY;
    for (int k = (j & 63); k < nEdges; k += 64) {
        int i1 = (k < n2) ? g_idx1[g_L2src[k]] : 0;
        float ev = g_als1[i1 * HEADS + h] + ald;
        ev = ev >= 0.f ? ev : 0.2f * ev;
        lmax = fmaxf(lmax, ev);
    }
    red[j] = lmax; __syncthreads();
    for (int s = 32; s >= 1; s >>= 1) {
        if ((j & 63) < s) red[j] = fmaxf(red[j], red[j + s]);
        __syncthreads();
    }
    if ((j & 63) == 0) m4[h] = red[j];
    __syncthreads();
    float lsum = 0.f;
    for (int k = (j & 63); k < nEdges; k += 64) {
        int i1 = (k < n2) ? g_idx1[g_L2src[k]] : 0;
        float ev = g_als1[i1 * HEADS + h] + ald;
        ev = ev >= 0.f ? ev : 0.2f * ev;
        lsum += expf(ev - m4[h]);
    }
    red[j] = lsum; __syncthreads();
    for (int s = 32; s >= 1; s >>= 1) {
        if ((j & 63) < s) red[j] += red[j + s];
        __syncthreads();
    }
    if ((j & 63) == 0) den4[h] = red[j];
    __syncthreads();
    float invden = 1.f / (den4[h] + 1e-16f);
    float mm = m4[h];
    float outv = 0.f;
    for (int k = 0; k < nEdges; k++) {
        int i1 = (k < n2) ? g_idx1[g_L2src[k]] : 0;
        float ev = g_als1[i1 * HEADS + h] + ald;
        ev = ev >= 0.f ? ev : 0.2f * ev;
        outv += expf(ev - mm) * invden * g_h1[i1 * HC + j];
    }
    outv += b1[j];
    outv = outv > 0.f ? outv : (expf(outv) - 1.f);           // ELU
    red[j] = outv * outv;
    for (int s = 128; s >= 1; s >>= 1) {
        __syncthreads();
        if (j < s) red[j] += red[j + s];
    }
    __syncthreads();
    float nv = fmaxf(sqrtf(red[0]), 1e-12f);
    g_ctx[j] = outv / nv;
}

// hmid = relu(ctx @ pw1 + pb1)
__global__ void k_mlp1(const float* __restrict__ pw1, const float* __restrict__ pb1) {
    __shared__ float c[HC];
    int t = threadIdx.x;
    for (int i = t; i < HC; i += blockDim.x) c[i] = g_ctx[i];
    __syncthreads();
    if (t < DIN) {
        float acc = pb1[t];
        #pragma unroll 8
        for (int k = 0; k < HC; k++) acc += c[k] * pw1[k * DIN + t];
        g_hmid[t] = fmaxf(acc, 0.f);
    }
}

// out = hmid @ pw2 + pb2  — float4 path (V % 4 == 0), the one big read: 64 x V
__global__ void k_out4(const float4* __restrict__ pw2, const float4* __restrict__ pb2,
                       float4* __restrict__ out, int V4, int V) {
    __shared__ float hm[DIN];
    if (threadIdx.x < DIN) hm[threadIdx.x] = g_hmid[threadIdx.x];
    __syncthreads();
    int v = blockIdx.x * blockDim.x + threadIdx.x;
    if (v < V4) {
        float4 acc = pb2[v];
        #pragma unroll
        for (int d = 0; d < DIN; d++) {
            float4 w = pw2[(long long)d * V4 + v];
            float hd = hm[d];
            acc.x += hd * w.x; acc.y += hd * w.y;
            acc.z += hd * w.z; acc.w += hd * w.w;
        }
        out[v] = acc;
    }
    (void)V;
}

// scalar fallback
__global__ void k_out(const float* __restrict__ pw2, const float* __restrict__ pb2,
                      float* __restrict__ out, int V) {
    __shared__ float hm[DIN];
    if (threadIdx.x < DIN) hm[threadIdx.x] = g_hmid[threadIdx.x];
    __syncthreads();
    int v = blockIdx.x * blockDim.x + threadIdx.x;
    if (v < V) {
        float acc = pb2[v];
        #pragma unroll
        for (int d = 0; d < DIN; d++) acc += hm[d] * pw2[(long long)d * V + v];
        out[v] = acc;
    }
}

// ------------------------------- launcher ----------------------------------
extern "C" void kernel_launch(void* const* d_in, const int* in_sizes, int n_in,
                              void* d_out, int out_size) {
    const int*   y   = (const int*)  d_in[0];
    const int*   ei  = (const int*)  d_in[1];
    const float* emb = (const float*)d_in[2];
    const float* W0  = (const float*)d_in[3];
    const float* as0 = (const float*)d_in[4];
    const float* ad0 = (const float*)d_in[5];
    const float* b0  = (const float*)d_in[6];
    const float* W1  = (const float*)d_in[7];
    const float* as1 = (const float*)d_in[8];
    const float* ad1 = (const float*)d_in[9];
    const float* b1  = (const float*)d_in[10];
    const float* pw1 = (const float*)d_in[11];
    const float* pb1 = (const float*)d_in[12];
    const float* pw2 = (const float*)d_in[13];
    const float* pb2 = (const float*)d_in[14];
    float* out = (float*)d_out;

    int N = in_sizes[0];
    int E = in_sizes[1] / 2;
    int V = in_sizes[14];
    const int* src = ei;        // edge_index row 0
    const int* dst = ei + E;    // edge_index row 1
    int nTarget = N - 1;

    k_init   <<<(N + 255) / 256, 256>>>(N);
    k_scan2  <<<(E + 255) / 256, 256>>>(src, dst, E, nTarget);
    k_buildS1<<<1, 256>>>(nTarget);
    k_scanE1 <<<(E + 255) / 256, 256>>>(src, dst, E);
    k_h0     <<<128, 256>>>(y, emb, W0, as0, ad0);
    k_layer1 <<<64, 256>>>(b0);
    k_h1     <<<64, 256>>>(W1, as1, ad1);
    k_layer2 <<<1, 256>>>(b1);
    k_mlp1   <<<1, 64>>>(pw1, pb1);
    if ((V & 3) == 0) {
        int V4 = V >> 2;
        k_out4<<<(V4 + 255) / 256, 256>>>((const float4*)pw2, (const float4*)pb2,
                                          (float4*)out, V4, V);
    } else {
        k_out <<<(V + 255) / 256, 256>>>(pw2, pb2, out, V);
    }
}